// round 14
// baseline (speedup 1.0000x reference)
#include <cuda_runtime.h>
#include <math.h>

#define NBLK 1216         // 2 waves of 4 CTAs/SM x 152 SMs: wave-2 backfills tail spread
#define NTHR 256
#define NCOL 256

#define FX_SCALE 1073741824.0   // 2^30 fixed-point scale

// 256 column accumulators, Q34.30 fixed point, plus a completion counter.
// Zero at module load; the last block resets them each call so graph replays
// stay deterministic.
__device__ unsigned long long g_acc[NCOL];
__device__ unsigned int g_count;

__global__ void __launch_bounds__(NTHR, 4)
colsq_fused_kernel(const float* __restrict__ d, long long n_f4,
                   float* __restrict__ out) {
    const int tid = threadIdx.x;
    const float4* __restrict__ p = (const float4*)d;

    // Stride in floats = gridDim*NTHR*4, a multiple of 256, so every thread
    // touches a fixed 4-column group.
    long long idx = (long long)blockIdx.x * NTHR + tid;
    const long long stride = (long long)gridDim.x * NTHR;

    float a0 = 0.f, a1 = 0.f, a2 = 0.f, a3 = 0.f;

    // Unroll x8, streaming (evict-first) loads.
    long long i = idx;
    for (; i + 7 * stride < n_f4; i += 8 * stride) {
        float4 v0 = __ldcs(&p[i]);
        float4 v1 = __ldcs(&p[i + stride]);
        float4 v2 = __ldcs(&p[i + 2 * stride]);
        float4 v3 = __ldcs(&p[i + 3 * stride]);
        float4 v4 = __ldcs(&p[i + 4 * stride]);
        float4 v5 = __ldcs(&p[i + 5 * stride]);
        float4 v6 = __ldcs(&p[i + 6 * stride]);
        float4 v7 = __ldcs(&p[i + 7 * stride]);
        a0 += v0.x * v0.x; a1 += v0.y * v0.y; a2 += v0.z * v0.z; a3 += v0.w * v0.w;
        a0 += v1.x * v1.x; a1 += v1.y * v1.y; a2 += v1.z * v1.z; a3 += v1.w * v1.w;
        a0 += v2.x * v2.x; a1 += v2.y * v2.y; a2 += v2.z * v2.z; a3 += v2.w * v2.w;
        a0 += v3.x * v3.x; a1 += v3.y * v3.y; a2 += v3.z * v3.z; a3 += v3.w * v3.w;
        a0 += v4.x * v4.x; a1 += v4.y * v4.y; a2 += v4.z * v4.z; a3 += v4.w * v4.w;
        a0 += v5.x * v5.x; a1 += v5.y * v5.y; a2 += v5.z * v5.z; a3 += v5.w * v5.w;
        a0 += v6.x * v6.x; a1 += v6.y * v6.y; a2 += v6.z * v6.z; a3 += v6.w * v6.w;
        a0 += v7.x * v7.x; a1 += v7.y * v7.y; a2 += v7.z * v7.z; a3 += v7.w * v7.w;
    }
    for (; i < n_f4; i += stride) {
        float4 v = __ldcs(&p[i]);
        a0 += v.x * v.x; a1 += v.y * v.y; a2 += v.z * v.z; a3 += v.w * v.w;
    }

    // Deterministic block reduction: 4 replicas of the 256-column vector.
    __shared__ float s[4][NCOL];
    const int c = (tid * 4) & (NCOL - 1);
    const int rep = tid >> 6;  // 0..3
    s[rep][c + 0] = a0;
    s[rep][c + 1] = a1;
    s[rep][c + 2] = a2;
    s[rep][c + 3] = a3;
    __syncthreads();

    // One thread per column: fold 4 replicas, convert to Q34.30 fixed point,
    // relaxed integer RED into the L2-resident column accumulator.
    // Integer addition is associative -> bit-deterministic result.
    float part = s[0][tid] + s[1][tid] + s[2][tid] + s[3][tid];
    long long fx = llrintf(part * (float)FX_SCALE);
    atomicAdd(&g_acc[tid], (unsigned long long)fx);

    // --- last-block-done, fence-free (no CCTL.IVALL) ---
    __shared__ bool isLast;
    __syncthreads();
    if (tid == 0) {
        unsigned int old;
        asm volatile("atom.add.release.gpu.u32 %0, [%1], %2;"
                     : "=r"(old) : "l"(&g_count), "r"(1u) : "memory");
        isLast = (old == (unsigned)(NBLK - 1));
    }
    __syncthreads();
    if (!isLast) return;

    if (tid == 0) {
        unsigned int tmp;
        asm volatile("ld.acquire.gpu.u32 %0, [%1];"
                     : "=r"(tmp) : "l"(&g_count) : "memory");
    }
    __syncthreads();

    // Epilogue: 2 KB from L2, reduce 256 -> 1, write scalar, reset state.
    unsigned long long raw = __ldcg(&g_acc[tid]);
    g_acc[tid] = 0ull;                         // reset for next graph replay

    double colsum = (double)(long long)raw * (1.0 / FX_SCALE);
    double diff = colsum - 1.0;

    __shared__ double red[NCOL];
    red[tid] = diff * diff;
    __syncthreads();

    #pragma unroll
    for (int off = NCOL / 2; off >= 32; off >>= 1) {
        if (tid < off) red[tid] += red[tid + off];
        __syncthreads();
    }
    if (tid < 32) {
        double v = red[tid];
        #pragma unroll
        for (int off = 16; off > 0; off >>= 1)
            v += __shfl_down_sync(0xFFFFFFFF, v, off);
        if (tid == 0) {
            out[0] = (float)(0.001 * sqrt(v));
            g_count = 0;                       // reset counter for next replay
        }
    }
}

extern "C" void kernel_launch(void* const* d_in, const int* in_sizes, int n_in,
                              void* d_out, int out_size) {
    const float* d = (const float*)d_in[0];
    float* out = (float*)d_out;
    long long n = (long long)in_sizes[0];      // 262144 * 256
    long long n_f4 = n / 4;

    colsq_fused_kernel<<<NBLK, NTHR>>>(d, n_f4, out);
}

// round 15
// speedup vs baseline: 1.0484x; 1.0484x over previous
#include <cuda_runtime.h>
#include <math.h>

#define NBLK 608          // 4 CTAs/SM x 152 SMs, single wave, 32 warps/SM (measured optimum)
#define NTHR 256
#define NCOL 256

#define FX_SCALE 1073741824.0   // 2^30 fixed-point scale

// 256 column accumulators, Q34.30 fixed point, plus a completion counter.
// Zero at module load; the last block resets them each call so graph replays
// stay deterministic.
__device__ unsigned long long g_acc[NCOL];
__device__ unsigned int g_count;

__global__ void __launch_bounds__(NTHR, 4)
colsq_fused_kernel(const float* __restrict__ d, long long n_f4,
                   float* __restrict__ out) {
    const int tid = threadIdx.x;
    const float4* __restrict__ p = (const float4*)d;

    // Dual-stream: read from both halves of the array each iteration so both
    // L2 dies / HBM stacks see even demand. half (in floats) = n/2 is a
    // multiple of 256, so the column-group mapping is identical for both
    // streams. Stride in floats = gridDim*NTHR*4 is a multiple of 256.
    const long long half = n_f4 >> 1;
    const float4* __restrict__ p2 = p + half;

    long long idx = (long long)blockIdx.x * NTHR + tid;
    const long long stride = (long long)gridDim.x * NTHR;

    float a0 = 0.f, a1 = 0.f, a2 = 0.f, a3 = 0.f;

    // 8 independent LDG.128 in flight per thread: 4 per half.
    long long i = idx;
    for (; i + 3 * stride < half; i += 4 * stride) {
        float4 v0 = __ldcs(&p[i]);
        float4 v1 = __ldcs(&p[i + stride]);
        float4 v2 = __ldcs(&p[i + 2 * stride]);
        float4 v3 = __ldcs(&p[i + 3 * stride]);
        float4 w0 = __ldcs(&p2[i]);
        float4 w1 = __ldcs(&p2[i + stride]);
        float4 w2 = __ldcs(&p2[i + 2 * stride]);
        float4 w3 = __ldcs(&p2[i + 3 * stride]);
        a0 += v0.x * v0.x; a1 += v0.y * v0.y; a2 += v0.z * v0.z; a3 += v0.w * v0.w;
        a0 += v1.x * v1.x; a1 += v1.y * v1.y; a2 += v1.z * v1.z; a3 += v1.w * v1.w;
        a0 += v2.x * v2.x; a1 += v2.y * v2.y; a2 += v2.z * v2.z; a3 += v2.w * v2.w;
        a0 += v3.x * v3.x; a1 += v3.y * v3.y; a2 += v3.z * v3.z; a3 += v3.w * v3.w;
        a0 += w0.x * w0.x; a1 += w0.y * w0.y; a2 += w0.z * w0.z; a3 += w0.w * w0.w;
        a0 += w1.x * w1.x; a1 += w1.y * w1.y; a2 += w1.z * w1.z; a3 += w1.w * w1.w;
        a0 += w2.x * w2.x; a1 += w2.y * w2.y; a2 += w2.z * w2.z; a3 += w2.w * w2.w;
        a0 += w3.x * w3.x; a1 += w3.y * w3.y; a2 += w3.z * w3.z; a3 += w3.w * w3.w;
    }
    for (; i < half; i += stride) {
        float4 v = __ldcs(&p[i]);
        float4 w = __ldcs(&p2[i]);
        a0 += v.x * v.x; a1 += v.y * v.y; a2 += v.z * v.z; a3 += v.w * v.w;
        a0 += w.x * w.x; a1 += w.y * w.y; a2 += w.z * w.z; a3 += w.w * w.w;
    }

    // Deterministic block reduction: 4 replicas of the 256-column vector.
    __shared__ float s[4][NCOL];
    const int c = (tid * 4) & (NCOL - 1);
    const int rep = tid >> 6;  // 0..3
    s[rep][c + 0] = a0;
    s[rep][c + 1] = a1;
    s[rep][c + 2] = a2;
    s[rep][c + 3] = a3;
    __syncthreads();

    // One thread per column: fold 4 replicas, convert to Q34.30 fixed point,
    // relaxed integer RED into the L2-resident column accumulator.
    // Integer addition is associative -> bit-deterministic result.
    float part = s[0][tid] + s[1][tid] + s[2][tid] + s[3][tid];
    long long fx = llrintf(part * (float)FX_SCALE);
    atomicAdd(&g_acc[tid], (unsigned long long)fx);

    // --- last-block-done, fence-free (no CCTL.IVALL) ---
    __shared__ bool isLast;
    __syncthreads();
    if (tid == 0) {
        unsigned int old;
        asm volatile("atom.add.release.gpu.u32 %0, [%1], %2;"
                     : "=r"(old) : "l"(&g_count), "r"(1u) : "memory");
        isLast = (old == (unsigned)(NBLK - 1));
    }
    __syncthreads();
    if (!isLast) return;

    if (tid == 0) {
        unsigned int tmp;
        asm volatile("ld.acquire.gpu.u32 %0, [%1];"
                     : "=r"(tmp) : "l"(&g_count) : "memory");
    }
    __syncthreads();

    // Epilogue: 2 KB from L2, reduce 256 -> 1, write scalar, reset state.
    unsigned long long raw = __ldcg(&g_acc[tid]);
    g_acc[tid] = 0ull;                         // reset for next graph replay

    double colsum = (double)(long long)raw * (1.0 / FX_SCALE);
    double diff = colsum - 1.0;

    __shared__ double red[NCOL];
    red[tid] = diff * diff;
    __syncthreads();

    #pragma unroll
    for (int off = NCOL / 2; off >= 32; off >>= 1) {
        if (tid < off) red[tid] += red[tid + off];
        __syncthreads();
    }
    if (tid < 32) {
        double v = red[tid];
        #pragma unroll
        for (int off = 16; off > 0; off >>= 1)
            v += __shfl_down_sync(0xFFFFFFFF, v, off);
        if (tid == 0) {
            out[0] = (float)(0.001 * sqrt(v));
            g_count = 0;                       // reset counter for next replay
        }
    }
}

extern "C" void kernel_launch(void* const* d_in, const int* in_sizes, int n_in,
                              void* d_out, int out_size) {
    const float* d = (const float*)d_in[0];
    float* out = (float*)d_out;
    long long n = (long long)in_sizes[0];      // 262144 * 256
    long long n_f4 = n / 4;

    colsq_fused_kernel<<<NBLK, NTHR>>>(d, n_f4, out);
}